// round 15
// baseline (speedup 1.0000x reference)
#include <cuda_runtime.h>
#include <cuda_bf16.h>
#include <cstdint>
#include <cstddef>

// ---------------------------------------------------------------------------
// Shapes (fixed): B=8, S=256, EMB=512, HID=256, NH=8, DH=32
// Outputs concat: cons[8] | hall[8] | M[8*256*256] | attn_weights[8*256*256]
// ---------------------------------------------------------------------------

#define Bn 8
#define Sn 256
#define EMB 512
#define HID 256
#define NHh 8
#define DHd 32
#define ROWS (Bn*Sn)          // 2048

typedef unsigned long long ULL;

// ===========================================================================
// f32x2 packed helpers
// ===========================================================================
__device__ __forceinline__ ULL pk2(float lo, float hi) {
    ULL r; asm("mov.b64 %0,{%1,%2};" : "=l"(r) : "f"(lo), "f"(hi)); return r;
}
__device__ __forceinline__ ULL fma2(ULL a, ULL b, ULL c) {
    ULL d; asm("fma.rn.f32x2 %0,%1,%2,%3;" : "=l"(d) : "l"(a), "l"(b), "l"(c)); return d;
}
__device__ __forceinline__ ULL mul2(ULL a, ULL b) {
    ULL d; asm("mul.rn.f32x2 %0,%1,%2;" : "=l"(d) : "l"(a), "l"(b)); return d;
}
__device__ __forceinline__ void unpk(ULL v, float& lo, float& hi) {
    asm("mov.b64 {%0,%1},%2;" : "=f"(lo), "=f"(hi) : "l"(v));
}

// ===========================================================================
// Scratch (__device__ globals; no allocs allowed)
// ===========================================================================
__device__ float g_h [ROWS*HID];     // h partial (K half 0)
__device__ float g_h2[ROWS*HID];     // h partial (K half 1)
__device__ float g_r [ROWS*HID];
__device__ float g_mf[ROWS*HID];
__device__ float g_qkv[ROWS*3*HID];
__device__ float g_ctx[ROWS*HID];
__device__ float g_a[ROWS*HID];
__device__ float g_b[ROWS*HID];
__device__ float g_probs[NHh*Bn*Sn*Sn];   // [h][b][t][s]

// ===========================================================================
// f32x2 SIMT GEMM core (round-3/10 PROVEN inner loop; do not touch).
//   C_tile[64,64] = A[64,K] @ W^T (+bias); 128 threads, 8x4 microtile, BK=16,
//   double-buffered smem.
// ===========================================================================
__device__ __forceinline__ void gemm_core_f32(const float* __restrict__ Ablk, int lda,
                                              const float* __restrict__ Wblk, int ldw,
                                              const float* __restrict__ biasblk,
                                              float* __restrict__ Cblk,
                                              int ldc, int K)
{
    __shared__ __align__(16) float As[2][16][68];
    __shared__ __align__(16) float Ws[2][16][68];
    const int tid = threadIdx.x;
    const int lrow = tid & 63;
    const int lk = (tid >> 6) << 3;   // 0 or 8
    const float* Ap = Ablk + (size_t)lrow * lda + lk;
    const float* Wp = Wblk + (size_t)lrow * ldw + lk;
    const int tx = tid & 15;
    const int ty = tid >> 4;

    ULL acc[4][4];
#pragma unroll
    for (int u = 0; u < 4; u++)
#pragma unroll
        for (int j = 0; j < 4; j++) acc[u][j] = 0ULL;

    float4 a0 = *(const float4*)(Ap);
    float4 a1 = *(const float4*)(Ap + 4);
    float4 w0 = *(const float4*)(Wp);
    float4 w1 = *(const float4*)(Wp + 4);
    As[0][lk + 0][lrow] = a0.x; As[0][lk + 1][lrow] = a0.y;
    As[0][lk + 2][lrow] = a0.z; As[0][lk + 3][lrow] = a0.w;
    As[0][lk + 4][lrow] = a1.x; As[0][lk + 5][lrow] = a1.y;
    As[0][lk + 6][lrow] = a1.z; As[0][lk + 7][lrow] = a1.w;
    Ws[0][lk + 0][lrow] = w0.x; Ws[0][lk + 1][lrow] = w0.y;
    Ws[0][lk + 2][lrow] = w0.z; Ws[0][lk + 3][lrow] = w0.w;
    Ws[0][lk + 4][lrow] = w1.x; Ws[0][lk + 5][lrow] = w1.y;
    Ws[0][lk + 6][lrow] = w1.z; Ws[0][lk + 7][lrow] = w1.w;
    __syncthreads();

    const int nt = K >> 4;
    for (int t = 0; t < nt; ++t) {
        const int cur = t & 1;
        if (t + 1 < nt) {
            const float* Ap2 = Ap + ((t + 1) << 4);
            const float* Wp2 = Wp + ((t + 1) << 4);
            a0 = *(const float4*)(Ap2);
            a1 = *(const float4*)(Ap2 + 4);
            w0 = *(const float4*)(Wp2);
            w1 = *(const float4*)(Wp2 + 4);
        }
#pragma unroll
        for (int kk = 0; kk < 16; ++kk) {
            ulonglong2 aA = *(const ulonglong2*)&As[cur][kk][ty << 3];
            ulonglong2 aB = *(const ulonglong2*)&As[cur][kk][(ty << 3) + 4];
            float4 bf = *(const float4*)&Ws[cur][kk][tx << 2];
            ULL b0 = pk2(bf.x, bf.x);
            ULL b1 = pk2(bf.y, bf.y);
            ULL b2 = pk2(bf.z, bf.z);
            ULL b3 = pk2(bf.w, bf.w);
            ULL ar[4] = {aA.x, aA.y, aB.x, aB.y};
#pragma unroll
            for (int u = 0; u < 4; u++) {
                acc[u][0] = fma2(ar[u], b0, acc[u][0]);
                acc[u][1] = fma2(ar[u], b1, acc[u][1]);
                acc[u][2] = fma2(ar[u], b2, acc[u][2]);
                acc[u][3] = fma2(ar[u], b3, acc[u][3]);
            }
        }
        if (t + 1 < nt) {
            const int nb = (t + 1) & 1;
            As[nb][lk + 0][lrow] = a0.x; As[nb][lk + 1][lrow] = a0.y;
            As[nb][lk + 2][lrow] = a0.z; As[nb][lk + 3][lrow] = a0.w;
            As[nb][lk + 4][lrow] = a1.x; As[nb][lk + 5][lrow] = a1.y;
            As[nb][lk + 6][lrow] = a1.z; As[nb][lk + 7][lrow] = a1.w;
            Ws[nb][lk + 0][lrow] = w0.x; Ws[nb][lk + 1][lrow] = w0.y;
            Ws[nb][lk + 2][lrow] = w0.z; Ws[nb][lk + 3][lrow] = w0.w;
            Ws[nb][lk + 4][lrow] = w1.x; Ws[nb][lk + 5][lrow] = w1.y;
            Ws[nb][lk + 6][lrow] = w1.z; Ws[nb][lk + 7][lrow] = w1.w;
            __syncthreads();
        }
    }

    float4 bz = make_float4(0.f, 0.f, 0.f, 0.f);
    if (biasblk) bz = *(const float4*)(biasblk + (tx << 2));
#pragma unroll
    for (int u = 0; u < 4; u++) {
        float4 lo4, hi4;
        unpk(acc[u][0], lo4.x, hi4.x);
        unpk(acc[u][1], lo4.y, hi4.y);
        unpk(acc[u][2], lo4.z, hi4.z);
        unpk(acc[u][3], lo4.w, hi4.w);
        lo4.x += bz.x; lo4.y += bz.y; lo4.z += bz.z; lo4.w += bz.w;
        hi4.x += bz.x; hi4.y += bz.y; hi4.z += bz.z; hi4.w += bz.w;
        int r0 = (ty << 3) + 2 * u;
        *(float4*)(Cblk + (size_t)r0 * ldc + (tx << 2)) = lo4;
        *(float4*)(Cblk + (size_t)(r0 + 1) * ldc + (tx << 2)) = hi4;
    }
}

// h GEMM with K split in two halves (z = K half), partials to h0/h1, no bias
__global__ __launch_bounds__(128) void gemm_h_kernel(const float* __restrict__ X,
                                                     const float* __restrict__ w1,
                                                     float* __restrict__ h0,
                                                     float* __restrict__ h1)
{
    int row0 = blockIdx.y << 6;
    int col0 = blockIdx.x << 6;
    int kz = blockIdx.z;
    float* outp = kz ? h1 : h0;
    gemm_core_f32(X + (size_t)row0 * EMB + kz * 256, EMB,
                  w1 + (size_t)col0 * EMB + kz * 256, EMB,
                  nullptr,
                  outp + (size_t)row0 * HID + col0, HID, 256);
}

// generic GEMM: C[M,N] = A@W^T + bias
__global__ __launch_bounds__(128) void gemm_f32_kernel(const float* __restrict__ A, int lda,
                                                       const float* __restrict__ W, int ldw,
                                                       const float* __restrict__ bias,
                                                       float* __restrict__ C, int ldc, int K)
{
    int row0 = blockIdx.y << 6;
    int col0 = blockIdx.x << 6;
    gemm_core_f32(A + (size_t)row0 * lda, lda,
                  W + (size_t)col0 * ldw, ldw,
                  bias ? bias + col0 : nullptr,
                  C + (size_t)row0 * ldc + col0, ldc, K);
}

// fused: from mf compute qkv (tiles 0..11), a (12..15), b (16..19)
__global__ __launch_bounds__(128) void gemm_fused_kernel(const float* __restrict__ mf,
                                                         const float* __restrict__ in_proj_w,
                                                         const float* __restrict__ in_proj_b,
                                                         const float* __restrict__ con_w1,
                                                         float* __restrict__ qkv,
                                                         float* __restrict__ a,
                                                         float* __restrict__ b)
{
    int row0 = blockIdx.y << 6;
    int cb = blockIdx.x;
    const float* Wblk; const float* biasblk; float* Cblk; int ldw, ldc;
    if (cb < 12) {
        int n0 = cb << 6;
        Wblk = in_proj_w + (size_t)n0 * HID; ldw = HID;
        biasblk = in_proj_b + n0;
        Cblk = qkv + (size_t)row0 * (3 * HID) + n0; ldc = 3 * HID;
    } else if (cb < 16) {
        int n0 = (cb - 12) << 6;
        Wblk = con_w1 + (size_t)n0 * (2 * HID); ldw = 2 * HID;
        biasblk = nullptr;
        Cblk = a + (size_t)row0 * HID + n0; ldc = HID;
    } else {
        int n0 = (cb - 16) << 6;
        Wblk = con_w1 + (size_t)n0 * (2 * HID) + HID; ldw = 2 * HID;
        biasblk = nullptr;
        Cblk = b + (size_t)row0 * HID + n0; ldc = HID;
    }
    gemm_core_f32(mf + (size_t)row0 * HID, HID, Wblk, ldw, biasblk, Cblk, ldc, HID);
}

// ===========================================================================
// LayerNorm(256)+ReLU, warp-per-row; h = h0 + h1 + enc_b1 summed here.
// ===========================================================================
__global__ void ln_relu_kernel(const float* __restrict__ h0,
                               const float* __restrict__ h1,
                               const float* __restrict__ b1v,
                               const float* __restrict__ g,
                               const float* __restrict__ beta,
                               float* __restrict__ r)
{
    int row = (blockIdx.x << 3) + (threadIdx.x >> 5);
    int lane = threadIdx.x & 31;
    const float* p0 = h0 + (size_t)row * HID;
    const float* p1 = h1 + (size_t)row * HID;
    float v[8];
    float s = 0.f, s2 = 0.f;
#pragma unroll
    for (int j = 0; j < 8; j++) {
        int c = lane + (j << 5);
        float x = p0[c] + p1[c] + b1v[c];
        v[j] = x;
        s += x; s2 += x * x;
    }
#pragma unroll
    for (int o = 16; o; o >>= 1) {
        s  += __shfl_xor_sync(0xffffffffu, s, o);
        s2 += __shfl_xor_sync(0xffffffffu, s2, o);
    }
    float mu = s * (1.f / 256.f);
    float var = fmaxf(s2 * (1.f / 256.f) - mu * mu, 0.f);
    float rstd = rsqrtf(var + 1e-5f);
    float* rr = r + (size_t)row * HID;
#pragma unroll
    for (int j = 0; j < 8; j++) {
        int c = lane + (j << 5);
        float y = (v[j] - mu) * rstd * g[c] + beta[c];
        rr[c] = fmaxf(y, 0.f);
    }
}

// ===========================================================================
// Attention (round-10 proven attn2): 128 blocks (2 query-halves x 64 (b,h)),
// 128 thr. Pass 1: online softmax -> ctx. Pass 2: recompute scores, write
// probs[h][b][t][s] = exp(score-m)/l/NH directly.
// ===========================================================================
__global__ __launch_bounds__(128) void attn2_kernel(const float* __restrict__ qkv,
                                                    float* __restrict__ ctx,
                                                    float* __restrict__ probs)
{
    extern __shared__ float sm[];
    float* Ks = sm;             // [256][32]
    float* Vs = sm + 256 * 32;  // [256][32]
    int bh = blockIdx.x >> 1;
    int half = blockIdx.x & 1;
    int b = bh >> 3, hd = bh & 7;
    int tid = threadIdx.x;
    int s = (half << 7) + tid;
    const float* base = qkv + (size_t)(b * Sn) * (3 * HID) + hd * DHd;

#pragma unroll
    for (int rr = 0; rr < 2; rr++) {
        int r = tid + rr * 128;
        const float4* krow = (const float4*)(base + (size_t)r * (3 * HID) + HID);
        const float4* vrow = (const float4*)(base + (size_t)r * (3 * HID) + 2 * HID);
        float4* kd = (float4*)(Ks + r * 32);
        float4* vd = (float4*)(Vs + r * 32);
#pragma unroll
        for (int i = 0; i < 8; i++) { kd[i] = krow[i]; vd[i] = vrow[i]; }
    }
    ULL q2[16];
    {
        const ulonglong2* qrow = (const ulonglong2*)(base + (size_t)s * (3 * HID));
#pragma unroll
        for (int u = 0; u < 8; u++) {
            ulonglong2 qv = qrow[u];
            q2[2 * u] = qv.x; q2[2 * u + 1] = qv.y;
        }
    }
    __syncthreads();

    const float scale = 0.17677669529663687f;   // 1/sqrt(32)
    float m = -1e30f, l = 0.f;
    ULL acc2[16];
#pragma unroll
    for (int d = 0; d < 16; d++) acc2[d] = 0ULL;

    for (int t = 0; t < Sn; t++) {
        const ulonglong2* k4 = (const ulonglong2*)(Ks + t * 32);
        ULL sd2 = 0ULL;
#pragma unroll
        for (int u = 0; u < 8; u++) {
            ulonglong2 kv = k4[u];
            sd2 = fma2(q2[2 * u], kv.x, sd2);
            sd2 = fma2(q2[2 * u + 1], kv.y, sd2);
        }
        float slo, shi;
        unpk(sd2, slo, shi);
        float sd = (slo + shi) * scale;
        float mn = fmaxf(m, sd);
        float corr = __expf(m - mn);
        float p = __expf(sd - mn);
        l = l * corr + p;
        ULL corr2 = pk2(corr, corr);
        ULL p2 = pk2(p, p);
        const ulonglong2* v4 = (const ulonglong2*)(Vs + t * 32);
#pragma unroll
        for (int u = 0; u < 8; u++) {
            ulonglong2 vv = v4[u];
            acc2[2 * u]     = fma2(p2, vv.x, mul2(acc2[2 * u], corr2));
            acc2[2 * u + 1] = fma2(p2, vv.y, mul2(acc2[2 * u + 1], corr2));
        }
        m = mn;
    }
    float invl = 1.f / l;
    ULL invl2 = pk2(invl, invl);
    ulonglong2* crow = (ulonglong2*)(ctx + (size_t)(b * Sn + s) * HID + hd * DHd);
#pragma unroll
    for (int u = 0; u < 8; u++) {
        ulonglong2 ov;
        ov.x = mul2(acc2[2 * u], invl2);
        ov.y = mul2(acc2[2 * u + 1], invl2);
        crow[u] = ov;
    }

    // pass 2: recompute scores, write final probs/NH (coalesced over s)
    float* pb = probs + ((size_t)(hd * Bn + b) * Sn) * Sn + s;
    float c1 = invl * 0.125f;
    for (int t = 0; t < Sn; t++) {
        const ulonglong2* k4 = (const ulonglong2*)(Ks + t * 32);
        ULL sd2 = 0ULL;
#pragma unroll
        for (int u = 0; u < 8; u++) {
            ulonglong2 kv = k4[u];
            sd2 = fma2(q2[2 * u], kv.x, sd2);
            sd2 = fma2(q2[2 * u + 1], kv.y, sd2);
        }
        float slo, shi;
        unpk(sd2, slo, shi);
        float sd = (slo + shi) * scale;
        pb[(size_t)t * Sn] = __expf(sd - m) * c1;
    }
}

// ===========================================================================
// attn_weights[b][s][t] = sum_h probs[h][b][t][s]
// ===========================================================================
__global__ void attnw_kernel(const float* __restrict__ probs,
                             float* __restrict__ out)
{
    __shared__ float tile[32][33];
    int b = blockIdx.z, t0 = blockIdx.x * 32, s0 = blockIdx.y * 32;
    int tx = threadIdx.x, ty = threadIdx.y;
#pragma unroll
    for (int r = 0; r < 4; r++) {
        int t = t0 + ty + r * 8;
        float sum = 0.f;
#pragma unroll
        for (int h = 0; h < 8; h++)
            sum += probs[((size_t)(h * Bn + b) * Sn + t) * Sn + s0 + tx];
        tile[ty + r * 8][tx] = sum;
    }
    __syncthreads();
#pragma unroll
    for (int r = 0; r < 4; r++) {
        int srow = s0 + ty + r * 8;
        out[((size_t)b * Sn + srow) * Sn + t0 + tx] = tile[tx][ty + r * 8];
    }
}

// ===========================================================================
// Merged tail: per-b block (grid 8, 256 threads):
//   pc = mean_s ctx[b]  ->  pooled = pc @ out_w^T + out_b
//   cons (tid<128) / hall (tid>=128) scalar MLPs -> out[0..15]
// ===========================================================================
__global__ void tail_kernel(const float* __restrict__ ctx,
                            const float* __restrict__ ow, const float* __restrict__ ob,
                            const float* __restrict__ cw1, const float* __restrict__ cb1,
                            const float* __restrict__ cw2, const float* __restrict__ cb2,
                            const float* __restrict__ hw1, const float* __restrict__ hb1,
                            const float* __restrict__ hw2, const float* __restrict__ hb2,
                            float* __restrict__ out)
{
    int b = blockIdx.x;
    int tid = threadIdx.x;
    int warp = tid >> 5, lane = tid & 31;
    __shared__ float pc[256];
    __shared__ float pooled[256];
    __shared__ float red[8];

    // 1. pooled ctx
    {
        float s = 0.f;
        const float* cb = ctx + (size_t)(b * Sn) * HID + tid;
        for (int t = 0; t < Sn; t++) s += cb[(size_t)t * HID];
        pc[tid] = s * (1.f / 256.f);
    }
    __syncthreads();

    // 2. pooled = pc @ out_w^T + out_b  (warp-dot per col, 8 warps stride)
    for (int c = warp; c < HID; c += 8) {
        const float* wrow = ow + (size_t)c * HID;
        float sum = 0.f;
#pragma unroll
        for (int j = 0; j < 8; j++) {
            int k = lane + (j << 5);
            sum += wrow[k] * pc[k];
        }
#pragma unroll
        for (int o = 16; o; o >>= 1) sum += __shfl_xor_sync(0xffffffffu, sum, o);
        if (lane == 0) pooled[c] = sum + ob[c];
    }
    __syncthreads();

    // 3. cons (tid<128) / hall (tid>=128)
    int which = tid >> 7;        // 0 = cons, 1 = hall
    int rloc = tid & 127;
    const float* w1 = which ? hw1 : cw1;
    const float* b1 = which ? hb1 : cb1;
    const float* w2 = which ? hw2 : cw2;
    float acc = b1[rloc];
    const float* wrow = w1 + (size_t)rloc * HID;
#pragma unroll 8
    for (int k = 0; k < HID; k++) acc += pooled[k] * wrow[k];
    float v = fmaxf(acc, 0.f) * w2[rloc];
#pragma unroll
    for (int o = 16; o; o >>= 1) v += __shfl_xor_sync(0xffffffffu, v, o);
    if (lane == 0) red[warp] = v;
    __syncthreads();
    if (tid == 0) {
        float sum = red[0] + red[1] + red[2] + red[3] + cb2[0];
        out[b] = 1.f / (1.f + __expf(-sum));
    } else if (tid == 128) {
        float sum = red[4] + red[5] + red[6] + red[7] + hb2[0];
        out[8 + b] = 1.f / (1.f + __expf(-sum));
    }
}

// ===========================================================================
// Pairwise consistency matrix (float4 smem, round-3 proven).
// Diagonal tiles also write the zero diagonal (validated rounds 12-13).
// ===========================================================================
#define PSTR 260
__global__ void pair2_kernel(const float* __restrict__ ga, const float* __restrict__ gb,
                             const float* __restrict__ b1, const float* __restrict__ w2,
                             const float* __restrict__ b2, float* __restrict__ M)
{
    int tj = blockIdx.x, ti = blockIdx.y, b = blockIdx.z;
    if (ti > tj) return;
    extern __shared__ float sm[];
    float* a_s = sm;                   // [32][PSTR]  (bias folded in)
    float* b_s = sm + 32 * PSTR;       // [32][PSTR]
    float* w2s = b_s + 32 * PSTR;      // [256]
    float* scs = w2s + 256;            // [32][33]
    int tid = threadIdx.x;
    {
        int r = tid >> 3;
        int cb = (tid & 7) * 32;
        const float4* asrc = (const float4*)(ga + (size_t)(b * Sn + ti * 32 + r) * HID + cb);
        const float4* bsrc = (const float4*)(gb + (size_t)(b * Sn + tj * 32 + r) * HID + cb);
#pragma unroll
        for (int u = 0; u < 8; u++) {
            int c = cb + u * 4;
            float4 av = asrc[u];
            float4 bb = *(const float4*)(b1 + c);
            av.x += bb.x; av.y += bb.y; av.z += bb.z; av.w += bb.w;
            *(float4*)&a_s[r * PSTR + c] = av;
            *(float4*)&b_s[r * PSTR + c] = bsrc[u];
        }
        w2s[tid] = w2[tid];
    }
    __syncthreads();

    int tx = tid & 31, ty = tid >> 5;
    float acc[4] = {0.f, 0.f, 0.f, 0.f};
    for (int c = 0; c < 256; c += 4) {
        float4 w = *(const float4*)&w2s[c];
        float4 bv = *(const float4*)&b_s[tx * PSTR + c];
#pragma unroll
        for (int ii = 0; ii < 4; ii++) {
            float4 av = *(const float4*)&a_s[(ty + 8 * ii) * PSTR + c];
            acc[ii] += fmaxf(av.x + bv.x, 0.f) * w.x
                     + fmaxf(av.y + bv.y, 0.f) * w.y
                     + fmaxf(av.z + bv.z, 0.f) * w.z
                     + fmaxf(av.w + bv.w, 0.f) * w.w;
        }
    }
    float bb2 = b2[0];
#pragma unroll
    for (int ii = 0; ii < 4; ii++) {
        int il = ty + 8 * ii;
        float sc = 1.f / (1.f + __expf(-(acc[ii] + bb2)));
        scs[il * 33 + tx] = ((ti * 32 + il) < (tj * 32 + tx)) ? sc : 0.f;
    }
    __syncthreads();

    float* Mb = M + (size_t)b * Sn * Sn;
    bool diag = (ti == tj);
#pragma unroll
    for (int ii = 0; ii < 4; ii++) {
        int il = ty + 8 * ii;
        if (!diag || il <= tx)   // diag tile: upper incl. zero diagonal
            Mb[(size_t)(ti * 32 + il) * Sn + tj * 32 + tx] = scs[il * 33 + tx];
        if (!diag || tx < il)    // diag tile: strict lower (transpose)
            Mb[(size_t)(tj * 32 + il) * Sn + ti * 32 + tx] = scs[tx * 33 + il];
    }
}

// ===========================================================================
// Host launcher
// ===========================================================================
extern "C" void kernel_launch(void* const* d_in, const int* in_sizes, int n_in,
                              void* d_out, int out_size)
{
    (void)in_sizes; (void)n_in; (void)out_size;
    const float* X        = (const float*)d_in[0];
    const float* enc_w1   = (const float*)d_in[1];
    const float* enc_b1   = (const float*)d_in[2];
    const float* ln_g     = (const float*)d_in[3];
    const float* ln_b     = (const float*)d_in[4];
    const float* enc_w2   = (const float*)d_in[5];
    const float* enc_b2   = (const float*)d_in[6];
    const float* in_proj_w= (const float*)d_in[7];
    const float* in_proj_b= (const float*)d_in[8];
    const float* out_w    = (const float*)d_in[9];
    const float* out_b    = (const float*)d_in[10];
    const float* cons_w1  = (const float*)d_in[11];
    const float* cons_b1  = (const float*)d_in[12];
    const float* cons_w2  = (const float*)d_in[13];
    const float* cons_b2  = (const float*)d_in[14];
    const float* hall_w1  = (const float*)d_in[15];
    const float* hall_b1  = (const float*)d_in[16];
    const float* hall_w2  = (const float*)d_in[17];
    const float* hall_b2  = (const float*)d_in[18];
    const float* con_w1   = (const float*)d_in[19];
    const float* con_b1   = (const float*)d_in[20];
    const float* con_w2   = (const float*)d_in[21];
    const float* con_b2   = (const float*)d_in[22];

    float* out = (float*)d_out;
    float* Mout  = out + 16;
    float* AWout = out + 16 + Bn * Sn * Sn;

    float *p_h, *p_h2, *p_r, *p_mf, *p_qkv, *p_ctx, *p_a, *p_b, *p_probs;
    cudaGetSymbolAddress((void**)&p_h, g_h);
    cudaGetSymbolAddress((void**)&p_h2, g_h2);
    cudaGetSymbolAddress((void**)&p_r, g_r);
    cudaGetSymbolAddress((void**)&p_mf, g_mf);
    cudaGetSymbolAddress((void**)&p_qkv, g_qkv);
    cudaGetSymbolAddress((void**)&p_ctx, g_ctx);
    cudaGetSymbolAddress((void**)&p_a, g_a);
    cudaGetSymbolAddress((void**)&p_b, g_b);
    cudaGetSymbolAddress((void**)&p_probs, g_probs);

    const int attn_smem = 2 * 256 * 32 * (int)sizeof(float);                    // 64 KB
    const int pair_smem = (2 * 32 * PSTR + 256 + 32 * 33) * (int)sizeof(float); // ~71.8 KB
    cudaFuncSetAttribute(attn2_kernel, cudaFuncAttributeMaxDynamicSharedMemorySize, attn_smem);
    cudaFuncSetAttribute(pair2_kernel, cudaFuncAttributeMaxDynamicSharedMemorySize, pair_smem);

    // 1. h partials = X @ enc_w1^T  (split-K2: 256 blocks)
    gemm_h_kernel<<<dim3(HID / 64, ROWS / 64, 2), 128>>>(X, enc_w1, p_h, p_h2);
    // 2. r = relu(LN(h0+h1+enc_b1))  (warp-per-row)
    ln_relu_kernel<<<ROWS / 8, 256>>>(p_h, p_h2, enc_b1, ln_g, ln_b, p_r);
    // 3. mf = r @ enc_w2^T + enc_b2
    gemm_f32_kernel<<<dim3(HID / 64, ROWS / 64), 128>>>(
        p_r, HID, enc_w2, HID, enc_b2, p_mf, HID, HID);
    // 4. fused: qkv | a | b from mf
    gemm_fused_kernel<<<dim3(20, ROWS / 64), 128>>>(p_mf, in_proj_w, in_proj_b, con_w1,
                                                    p_qkv, p_a, p_b);
    // 5. attention (round-10 attn2) -> ctx, probs
    attn2_kernel<<<128, 128, attn_smem>>>(p_qkv, p_ctx, p_probs);
    // 6. merged tail: pooled ctx -> pooled -> cons/hall
    tail_kernel<<<Bn, 256>>>(p_ctx, out_w, out_b,
                             cons_w1, cons_b1, cons_w2, cons_b2,
                             hall_w1, hall_b1, hall_w2, hall_b2, out);
    // 7. attn_weights
    attnw_kernel<<<dim3(8, 8, 8), dim3(32, 8)>>>(p_probs, AWout);
    // 8. pairwise M (diag folded in; zero_diag launch removed)
    pair2_kernel<<<dim3(8, 8, 8), 256, pair_smem>>>(p_a, p_b, con_b1, con_w2, con_b2, Mout);
}

// round 16
// speedup vs baseline: 1.0613x; 1.0613x over previous
#include <cuda_runtime.h>
#include <cuda_bf16.h>
#include <cstdint>
#include <cstddef>

// ---------------------------------------------------------------------------
// Shapes (fixed): B=8, S=256, EMB=512, HID=256, NH=8, DH=32
// Outputs concat: cons[8] | hall[8] | M[8*256*256] | attn_weights[8*256*256]
// ---------------------------------------------------------------------------

#define Bn 8
#define Sn 256
#define EMB 512
#define HID 256
#define NHh 8
#define DHd 32
#define ROWS (Bn*Sn)          // 2048

typedef unsigned long long ULL;

// ===========================================================================
// f32x2 packed helpers
// ===========================================================================
__device__ __forceinline__ ULL pk2(float lo, float hi) {
    ULL r; asm("mov.b64 %0,{%1,%2};" : "=l"(r) : "f"(lo), "f"(hi)); return r;
}
__device__ __forceinline__ ULL fma2(ULL a, ULL b, ULL c) {
    ULL d; asm("fma.rn.f32x2 %0,%1,%2,%3;" : "=l"(d) : "l"(a), "l"(b), "l"(c)); return d;
}
__device__ __forceinline__ ULL mul2(ULL a, ULL b) {
    ULL d; asm("mul.rn.f32x2 %0,%1,%2;" : "=l"(d) : "l"(a), "l"(b)); return d;
}
__device__ __forceinline__ void unpk(ULL v, float& lo, float& hi) {
    asm("mov.b64 {%0,%1},%2;" : "=f"(lo), "=f"(hi) : "l"(v));
}

// ===========================================================================
// Scratch (__device__ globals; no allocs allowed)
// ===========================================================================
__device__ float g_h [ROWS*HID];     // h partial (K half 0)
__device__ float g_h2[ROWS*HID];     // h partial (K half 1)
__device__ float g_r [ROWS*HID];
__device__ float g_mf[ROWS*HID];
__device__ float g_qkv[ROWS*3*HID];
__device__ float g_ctx[ROWS*HID];
__device__ float g_a[ROWS*HID];
__device__ float g_b[ROWS*HID];
__device__ float g_probs[NHh*Bn*Sn*Sn];   // [h][b][t][s]
__device__ float g_pc[Bn*HID];            // pooled ctx
__device__ float g_pooled[Bn*HID];

// ===========================================================================
// f32x2 SIMT GEMM core (round-3/10 PROVEN inner loop; do not touch).
//   C_tile[64,64] = A[64,K] @ W^T (+bias); 128 threads, 8x4 microtile, BK=16,
//   double-buffered smem.
// ===========================================================================
__device__ __forceinline__ void gemm_core_f32(const float* __restrict__ Ablk, int lda,
                                              const float* __restrict__ Wblk, int ldw,
                                              const float* __restrict__ biasblk,
                                              float* __restrict__ Cblk,
                                              int ldc, int K)
{
    __shared__ __align__(16) float As[2][16][68];
    __shared__ __align__(16) float Ws[2][16][68];
    const int tid = threadIdx.x;
    const int lrow = tid & 63;
    const int lk = (tid >> 6) << 3;   // 0 or 8
    const float* Ap = Ablk + (size_t)lrow * lda + lk;
    const float* Wp = Wblk + (size_t)lrow * ldw + lk;
    const int tx = tid & 15;
    const int ty = tid >> 4;

    ULL acc[4][4];
#pragma unroll
    for (int u = 0; u < 4; u++)
#pragma unroll
        for (int j = 0; j < 4; j++) acc[u][j] = 0ULL;

    float4 a0 = *(const float4*)(Ap);
    float4 a1 = *(const float4*)(Ap + 4);
    float4 w0 = *(const float4*)(Wp);
    float4 w1 = *(const float4*)(Wp + 4);
    As[0][lk + 0][lrow] = a0.x; As[0][lk + 1][lrow] = a0.y;
    As[0][lk + 2][lrow] = a0.z; As[0][lk + 3][lrow] = a0.w;
    As[0][lk + 4][lrow] = a1.x; As[0][lk + 5][lrow] = a1.y;
    As[0][lk + 6][lrow] = a1.z; As[0][lk + 7][lrow] = a1.w;
    Ws[0][lk + 0][lrow] = w0.x; Ws[0][lk + 1][lrow] = w0.y;
    Ws[0][lk + 2][lrow] = w0.z; Ws[0][lk + 3][lrow] = w0.w;
    Ws[0][lk + 4][lrow] = w1.x; Ws[0][lk + 5][lrow] = w1.y;
    Ws[0][lk + 6][lrow] = w1.z; Ws[0][lk + 7][lrow] = w1.w;
    __syncthreads();

    const int nt = K >> 4;
    for (int t = 0; t < nt; ++t) {
        const int cur = t & 1;
        if (t + 1 < nt) {
            const float* Ap2 = Ap + ((t + 1) << 4);
            const float* Wp2 = Wp + ((t + 1) << 4);
            a0 = *(const float4*)(Ap2);
            a1 = *(const float4*)(Ap2 + 4);
            w0 = *(const float4*)(Wp2);
            w1 = *(const float4*)(Wp2 + 4);
        }
#pragma unroll
        for (int kk = 0; kk < 16; ++kk) {
            ulonglong2 aA = *(const ulonglong2*)&As[cur][kk][ty << 3];
            ulonglong2 aB = *(const ulonglong2*)&As[cur][kk][(ty << 3) + 4];
            float4 bf = *(const float4*)&Ws[cur][kk][tx << 2];
            ULL b0 = pk2(bf.x, bf.x);
            ULL b1 = pk2(bf.y, bf.y);
            ULL b2 = pk2(bf.z, bf.z);
            ULL b3 = pk2(bf.w, bf.w);
            ULL ar[4] = {aA.x, aA.y, aB.x, aB.y};
#pragma unroll
            for (int u = 0; u < 4; u++) {
                acc[u][0] = fma2(ar[u], b0, acc[u][0]);
                acc[u][1] = fma2(ar[u], b1, acc[u][1]);
                acc[u][2] = fma2(ar[u], b2, acc[u][2]);
                acc[u][3] = fma2(ar[u], b3, acc[u][3]);
            }
        }
        if (t + 1 < nt) {
            const int nb = (t + 1) & 1;
            As[nb][lk + 0][lrow] = a0.x; As[nb][lk + 1][lrow] = a0.y;
            As[nb][lk + 2][lrow] = a0.z; As[nb][lk + 3][lrow] = a0.w;
            As[nb][lk + 4][lrow] = a1.x; As[nb][lk + 5][lrow] = a1.y;
            As[nb][lk + 6][lrow] = a1.z; As[nb][lk + 7][lrow] = a1.w;
            Ws[nb][lk + 0][lrow] = w0.x; Ws[nb][lk + 1][lrow] = w0.y;
            Ws[nb][lk + 2][lrow] = w0.z; Ws[nb][lk + 3][lrow] = w0.w;
            Ws[nb][lk + 4][lrow] = w1.x; Ws[nb][lk + 5][lrow] = w1.y;
            Ws[nb][lk + 6][lrow] = w1.z; Ws[nb][lk + 7][lrow] = w1.w;
            __syncthreads();
        }
    }

    float4 bz = make_float4(0.f, 0.f, 0.f, 0.f);
    if (biasblk) bz = *(const float4*)(biasblk + (tx << 2));
#pragma unroll
    for (int u = 0; u < 4; u++) {
        float4 lo4, hi4;
        unpk(acc[u][0], lo4.x, hi4.x);
        unpk(acc[u][1], lo4.y, hi4.y);
        unpk(acc[u][2], lo4.z, hi4.z);
        unpk(acc[u][3], lo4.w, hi4.w);
        lo4.x += bz.x; lo4.y += bz.y; lo4.z += bz.z; lo4.w += bz.w;
        hi4.x += bz.x; hi4.y += bz.y; hi4.z += bz.z; hi4.w += bz.w;
        int r0 = (ty << 3) + 2 * u;
        *(float4*)(Cblk + (size_t)r0 * ldc + (tx << 2)) = lo4;
        *(float4*)(Cblk + (size_t)(r0 + 1) * ldc + (tx << 2)) = hi4;
    }
}

// h GEMM with K split in two halves (z = K half), partials to h0/h1, no bias
__global__ __launch_bounds__(128) void gemm_h_kernel(const float* __restrict__ X,
                                                     const float* __restrict__ w1,
                                                     float* __restrict__ h0,
                                                     float* __restrict__ h1)
{
    int row0 = blockIdx.y << 6;
    int col0 = blockIdx.x << 6;
    int kz = blockIdx.z;
    float* outp = kz ? h1 : h0;
    gemm_core_f32(X + (size_t)row0 * EMB + kz * 256, EMB,
                  w1 + (size_t)col0 * EMB + kz * 256, EMB,
                  nullptr,
                  outp + (size_t)row0 * HID + col0, HID, 256);
}

// generic GEMM: C[M,N] = A@W^T + bias
__global__ __launch_bounds__(128) void gemm_f32_kernel(const float* __restrict__ A, int lda,
                                                       const float* __restrict__ W, int ldw,
                                                       const float* __restrict__ bias,
                                                       float* __restrict__ C, int ldc, int K)
{
    int row0 = blockIdx.y << 6;
    int col0 = blockIdx.x << 6;
    gemm_core_f32(A + (size_t)row0 * lda, lda,
                  W + (size_t)col0 * ldw, ldw,
                  bias ? bias + col0 : nullptr,
                  C + (size_t)row0 * ldc + col0, ldc, K);
}

// fused: from mf compute qkv (tiles 0..11), a (12..15), b (16..19)
__global__ __launch_bounds__(128) void gemm_fused_kernel(const float* __restrict__ mf,
                                                         const float* __restrict__ in_proj_w,
                                                         const float* __restrict__ in_proj_b,
                                                         const float* __restrict__ con_w1,
                                                         float* __restrict__ qkv,
                                                         float* __restrict__ a,
                                                         float* __restrict__ b)
{
    int row0 = blockIdx.y << 6;
    int cb = blockIdx.x;
    const float* Wblk; const float* biasblk; float* Cblk; int ldw, ldc;
    if (cb < 12) {
        int n0 = cb << 6;
        Wblk = in_proj_w + (size_t)n0 * HID; ldw = HID;
        biasblk = in_proj_b + n0;
        Cblk = qkv + (size_t)row0 * (3 * HID) + n0; ldc = 3 * HID;
    } else if (cb < 16) {
        int n0 = (cb - 12) << 6;
        Wblk = con_w1 + (size_t)n0 * (2 * HID); ldw = 2 * HID;
        biasblk = nullptr;
        Cblk = a + (size_t)row0 * HID + n0; ldc = HID;
    } else {
        int n0 = (cb - 16) << 6;
        Wblk = con_w1 + (size_t)n0 * (2 * HID) + HID; ldw = 2 * HID;
        biasblk = nullptr;
        Cblk = b + (size_t)row0 * HID + n0; ldc = HID;
    }
    gemm_core_f32(mf + (size_t)row0 * HID, HID, Wblk, ldw, biasblk, Cblk, ldc, HID);
}

// ===========================================================================
// LayerNorm(256)+ReLU, warp-per-row; h = h0 + h1 + enc_b1 summed here.
// ===========================================================================
__global__ void ln_relu_kernel(const float* __restrict__ h0,
                               const float* __restrict__ h1,
                               const float* __restrict__ b1v,
                               const float* __restrict__ g,
                               const float* __restrict__ beta,
                               float* __restrict__ r)
{
    int row = (blockIdx.x << 3) + (threadIdx.x >> 5);
    int lane = threadIdx.x & 31;
    const float* p0 = h0 + (size_t)row * HID;
    const float* p1 = h1 + (size_t)row * HID;
    float v[8];
    float s = 0.f, s2 = 0.f;
#pragma unroll
    for (int j = 0; j < 8; j++) {
        int c = lane + (j << 5);
        float x = p0[c] + p1[c] + b1v[c];
        v[j] = x;
        s += x; s2 += x * x;
    }
#pragma unroll
    for (int o = 16; o; o >>= 1) {
        s  += __shfl_xor_sync(0xffffffffu, s, o);
        s2 += __shfl_xor_sync(0xffffffffu, s2, o);
    }
    float mu = s * (1.f / 256.f);
    float var = fmaxf(s2 * (1.f / 256.f) - mu * mu, 0.f);
    float rstd = rsqrtf(var + 1e-5f);
    float* rr = r + (size_t)row * HID;
#pragma unroll
    for (int j = 0; j < 8; j++) {
        int c = lane + (j << 5);
        float y = (v[j] - mu) * rstd * g[c] + beta[c];
        rr[c] = fmaxf(y, 0.f);
    }
}

// ===========================================================================
// Attention (f32x2): 128 blocks (2 query-halves x 64 (b,h)), 128 thr.
// Pass 1: online softmax -> ctx (fp32). Pass 2: recompute scores, write
// probs[h][b][t][s] = exp(score-m)/l/NH directly (single write, no stash).
// ===========================================================================
__global__ __launch_bounds__(128) void attn2_kernel(const float* __restrict__ qkv,
                                                    float* __restrict__ ctx,
                                                    float* __restrict__ probs)
{
    extern __shared__ float sm[];
    float* Ks = sm;             // [256][32]
    float* Vs = sm + 256 * 32;  // [256][32]
    int bh = blockIdx.x >> 1;
    int half = blockIdx.x & 1;
    int b = bh >> 3, hd = bh & 7;
    int tid = threadIdx.x;
    int s = (half << 7) + tid;
    const float* base = qkv + (size_t)(b * Sn) * (3 * HID) + hd * DHd;

#pragma unroll
    for (int rr = 0; rr < 2; rr++) {
        int r = tid + rr * 128;
        const float4* krow = (const float4*)(base + (size_t)r * (3 * HID) + HID);
        const float4* vrow = (const float4*)(base + (size_t)r * (3 * HID) + 2 * HID);
        float4* kd = (float4*)(Ks + r * 32);
        float4* vd = (float4*)(Vs + r * 32);
#pragma unroll
        for (int i = 0; i < 8; i++) { kd[i] = krow[i]; vd[i] = vrow[i]; }
    }
    ULL q2[16];
    {
        const ulonglong2* qrow = (const ulonglong2*)(base + (size_t)s * (3 * HID));
#pragma unroll
        for (int u = 0; u < 8; u++) {
            ulonglong2 qv = qrow[u];
            q2[2 * u] = qv.x; q2[2 * u + 1] = qv.y;
        }
    }
    __syncthreads();

    const float scale = 0.17677669529663687f;   // 1/sqrt(32)
    float m = -1e30f, l = 0.f;
    ULL acc2[16];
#pragma unroll
    for (int d = 0; d < 16; d++) acc2[d] = 0ULL;

    for (int t = 0; t < Sn; t++) {
        const ulonglong2* k4 = (const ulonglong2*)(Ks + t * 32);
        ULL sd2 = 0ULL;
#pragma unroll
        for (int u = 0; u < 8; u++) {
            ulonglong2 kv = k4[u];
            sd2 = fma2(q2[2 * u], kv.x, sd2);
            sd2 = fma2(q2[2 * u + 1], kv.y, sd2);
        }
        float slo, shi;
        unpk(sd2, slo, shi);
        float sd = (slo + shi) * scale;
        float mn = fmaxf(m, sd);
        float corr = __expf(m - mn);
        float p = __expf(sd - mn);
        l = l * corr + p;
        ULL corr2 = pk2(corr, corr);
        ULL p2 = pk2(p, p);
        const ulonglong2* v4 = (const ulonglong2*)(Vs + t * 32);
#pragma unroll
        for (int u = 0; u < 8; u++) {
            ulonglong2 vv = v4[u];
            acc2[2 * u]     = fma2(p2, vv.x, mul2(acc2[2 * u], corr2));
            acc2[2 * u + 1] = fma2(p2, vv.y, mul2(acc2[2 * u + 1], corr2));
        }
        m = mn;
    }
    float invl = 1.f / l;
    ULL invl2 = pk2(invl, invl);
    ulonglong2* crow = (ulonglong2*)(ctx + (size_t)(b * Sn + s) * HID + hd * DHd);
#pragma unroll
    for (int u = 0; u < 8; u++) {
        ulonglong2 ov;
        ov.x = mul2(acc2[2 * u], invl2);
        ov.y = mul2(acc2[2 * u + 1], invl2);
        crow[u] = ov;
    }

    // pass 2: recompute scores, write final probs/NH (coalesced over s)
    float* pb = probs + ((size_t)(hd * Bn + b) * Sn) * Sn + s;
    float c1 = invl * 0.125f;
    for (int t = 0; t < Sn; t++) {
        const ulonglong2* k4 = (const ulonglong2*)(Ks + t * 32);
        ULL sd2 = 0ULL;
#pragma unroll
        for (int u = 0; u < 8; u++) {
            ulonglong2 kv = k4[u];
            sd2 = fma2(q2[2 * u], kv.x, sd2);
            sd2 = fma2(q2[2 * u + 1], kv.y, sd2);
        }
        float slo, shi;
        unpk(sd2, slo, shi);
        float sd = (slo + shi) * scale;
        pb[(size_t)t * Sn] = __expf(sd - m) * c1;
    }
}

// ===========================================================================
// attn_weights[b][s][t] = sum_h probs[h][b][t][s]
// ===========================================================================
__global__ void attnw_kernel(const float* __restrict__ probs,
                             float* __restrict__ out)
{
    __shared__ float tile[32][33];
    int b = blockIdx.z, t0 = blockIdx.x * 32, s0 = blockIdx.y * 32;
    int tx = threadIdx.x, ty = threadIdx.y;
#pragma unroll
    for (int r = 0; r < 4; r++) {
        int t = t0 + ty + r * 8;
        float sum = 0.f;
#pragma unroll
        for (int h = 0; h < 8; h++)
            sum += probs[((size_t)(h * Bn + b) * Sn + t) * Sn + s0 + tx];
        tile[ty + r * 8][tx] = sum;
    }
    __syncthreads();
#pragma unroll
    for (int r = 0; r < 4; r++) {
        int srow = s0 + ty + r * 8;
        out[((size_t)b * Sn + srow) * Sn + t0 + tx] = tile[tx][ty + r * 8];
    }
}

// ===========================================================================
// pooled_ctx[b][c] = mean_s ctx[b][s][c]; pooled via mini-GEMM (linearity).
// ===========================================================================
__global__ void pool_ctx_kernel(const float* __restrict__ ctx, float* __restrict__ pc)
{
    int b = blockIdx.x, c = threadIdx.x;
    float s = 0.f;
    for (int t = 0; t < Sn; t++) s += ctx[(size_t)(b * Sn + t) * HID + c];
    pc[b * HID + c] = s * (1.f / 256.f);
}

__global__ void head_gemm_kernel(const float* __restrict__ pc,
                                 const float* __restrict__ ow,
                                 const float* __restrict__ ob,
                                 float* __restrict__ pooled)
{
    int b = blockIdx.x;
    int tid = threadIdx.x;
    int warp = tid >> 5, lane = tid & 31;
    __shared__ float ps[256];
    ps[tid] = pc[b * HID + tid];
    __syncthreads();
    for (int c = warp; c < HID; c += 8) {
        const float* wrow = ow + (size_t)c * HID;
        float sum = 0.f;
#pragma unroll
        for (int j = 0; j < 8; j++) {
            int k = lane + (j << 5);
            sum += wrow[k] * ps[k];
        }
#pragma unroll
        for (int o = 16; o; o >>= 1) sum += __shfl_xor_sync(0xffffffffu, sum, o);
        if (lane == 0) pooled[b * HID + c] = sum + ob[c];
    }
}

__global__ void head_mlp_kernel(const float* __restrict__ pooled,
                                const float* __restrict__ cw1, const float* __restrict__ cb1,
                                const float* __restrict__ cw2, const float* __restrict__ cb2,
                                const float* __restrict__ hw1, const float* __restrict__ hb1,
                                const float* __restrict__ hw2, const float* __restrict__ hb2,
                                float* __restrict__ out)
{
    int b = blockIdx.x >> 1;
    int which = blockIdx.x & 1;
    const float* w1 = which ? hw1 : cw1;
    const float* b1 = which ? hb1 : cb1;
    const float* w2 = which ? hw2 : cw2;
    const float* b2 = which ? hb2 : cb2;
    int tid = threadIdx.x;
    __shared__ float p[256];
    p[tid] = pooled[b * HID + tid];
    p[tid + 128] = pooled[b * HID + tid + 128];
    __syncthreads();
    float acc = b1[tid];
    const float* wrow = w1 + (size_t)tid * HID;
#pragma unroll 8
    for (int k = 0; k < HID; k++) acc += p[k] * wrow[k];
    float v = fmaxf(acc, 0.f) * w2[tid];
#pragma unroll
    for (int o = 16; o; o >>= 1) v += __shfl_xor_sync(0xffffffffu, v, o);
    __shared__ float rs[4];
    if ((tid & 31) == 0) rs[tid >> 5] = v;
    __syncthreads();
    if (tid == 0) {
        float sum = rs[0] + rs[1] + rs[2] + rs[3] + b2[0];
        out[which * 8 + b] = 1.f / (1.f + __expf(-sum));
    }
}

__global__ void zero_diag_kernel(float* __restrict__ M)
{
    int b = blockIdx.x, i = threadIdx.x;
    M[(size_t)b * Sn * Sn + (size_t)i * Sn + i] = 0.f;
}

// ===========================================================================
// Pairwise consistency matrix (float4 smem); round-3 proven.
// ===========================================================================
#define PSTR 260
__global__ void pair2_kernel(const float* __restrict__ ga, const float* __restrict__ gb,
                             const float* __restrict__ b1, const float* __restrict__ w2,
                             const float* __restrict__ b2, float* __restrict__ M)
{
    int tj = blockIdx.x, ti = blockIdx.y, b = blockIdx.z;
    if (ti > tj) return;
    extern __shared__ float sm[];
    float* a_s = sm;                   // [32][PSTR]  (bias folded in)
    float* b_s = sm + 32 * PSTR;       // [32][PSTR]
    float* w2s = b_s + 32 * PSTR;      // [256]
    float* scs = w2s + 256;            // [32][33]
    int tid = threadIdx.x;
    {
        int r = tid >> 3;
        int cb = (tid & 7) * 32;
        const float4* asrc = (const float4*)(ga + (size_t)(b * Sn + ti * 32 + r) * HID + cb);
        const float4* bsrc = (const float4*)(gb + (size_t)(b * Sn + tj * 32 + r) * HID + cb);
#pragma unroll
        for (int u = 0; u < 8; u++) {
            int c = cb + u * 4;
            float4 av = asrc[u];
            float4 bb = *(const float4*)(b1 + c);
            av.x += bb.x; av.y += bb.y; av.z += bb.z; av.w += bb.w;
            *(float4*)&a_s[r * PSTR + c] = av;
            *(float4*)&b_s[r * PSTR + c] = bsrc[u];
        }
        w2s[tid] = w2[tid];
    }
    __syncthreads();

    int tx = tid & 31, ty = tid >> 5;
    float acc[4] = {0.f, 0.f, 0.f, 0.f};
    for (int c = 0; c < 256; c += 4) {
        float4 w = *(const float4*)&w2s[c];
        float4 bv = *(const float4*)&b_s[tx * PSTR + c];
#pragma unroll
        for (int ii = 0; ii < 4; ii++) {
            float4 av = *(const float4*)&a_s[(ty + 8 * ii) * PSTR + c];
            acc[ii] += fmaxf(av.x + bv.x, 0.f) * w.x
                     + fmaxf(av.y + bv.y, 0.f) * w.y
                     + fmaxf(av.z + bv.z, 0.f) * w.z
                     + fmaxf(av.w + bv.w, 0.f) * w.w;
        }
    }
    float bb2 = b2[0];
#pragma unroll
    for (int ii = 0; ii < 4; ii++) {
        int il = ty + 8 * ii;
        float sc = 1.f / (1.f + __expf(-(acc[ii] + bb2)));
        scs[il * 33 + tx] = ((ti * 32 + il) < (tj * 32 + tx)) ? sc : 0.f;
    }
    __syncthreads();

    float* Mb = M + (size_t)b * Sn * Sn;
    bool diag = (ti == tj);
#pragma unroll
    for (int ii = 0; ii < 4; ii++) {
        int il = ty + 8 * ii;
        if (!diag || il < tx)
            Mb[(size_t)(ti * 32 + il) * Sn + tj * 32 + tx] = scs[il * 33 + tx];
        if (!diag || tx < il)
            Mb[(size_t)(tj * 32 + il) * Sn + ti * 32 + tx] = scs[tx * 33 + il];
    }
}

// ===========================================================================
// Host launcher
// ===========================================================================
extern "C" void kernel_launch(void* const* d_in, const int* in_sizes, int n_in,
                              void* d_out, int out_size)
{
    (void)in_sizes; (void)n_in; (void)out_size;
    const float* X        = (const float*)d_in[0];
    const float* enc_w1   = (const float*)d_in[1];
    const float* enc_b1   = (const float*)d_in[2];
    const float* ln_g     = (const float*)d_in[3];
    const float* ln_b     = (const float*)d_in[4];
    const float* enc_w2   = (const float*)d_in[5];
    const float* enc_b2   = (const float*)d_in[6];
    const float* in_proj_w= (const float*)d_in[7];
    const float* in_proj_b= (const float*)d_in[8];
    const float* out_w    = (const float*)d_in[9];
    const float* out_b    = (const float*)d_in[10];
    const float* cons_w1  = (const float*)d_in[11];
    const float* cons_b1  = (const float*)d_in[12];
    const float* cons_w2  = (const float*)d_in[13];
    const float* cons_b2  = (const float*)d_in[14];
    const float* hall_w1  = (const float*)d_in[15];
    const float* hall_b1  = (const float*)d_in[16];
    const float* hall_w2  = (const float*)d_in[17];
    const float* hall_b2  = (const float*)d_in[18];
    const float* con_w1   = (const float*)d_in[19];
    const float* con_b1   = (const float*)d_in[20];
    const float* con_w2   = (const float*)d_in[21];
    const float* con_b2   = (const float*)d_in[22];

    float* out = (float*)d_out;
    float* Mout  = out + 16;
    float* AWout = out + 16 + Bn * Sn * Sn;

    float *p_h, *p_h2, *p_r, *p_mf, *p_qkv, *p_ctx, *p_a, *p_b, *p_probs, *p_pc, *p_pooled;
    cudaGetSymbolAddress((void**)&p_h, g_h);
    cudaGetSymbolAddress((void**)&p_h2, g_h2);
    cudaGetSymbolAddress((void**)&p_r, g_r);
    cudaGetSymbolAddress((void**)&p_mf, g_mf);
    cudaGetSymbolAddress((void**)&p_qkv, g_qkv);
    cudaGetSymbolAddress((void**)&p_ctx, g_ctx);
    cudaGetSymbolAddress((void**)&p_a, g_a);
    cudaGetSymbolAddress((void**)&p_b, g_b);
    cudaGetSymbolAddress((void**)&p_probs, g_probs);
    cudaGetSymbolAddress((void**)&p_pc, g_pc);
    cudaGetSymbolAddress((void**)&p_pooled, g_pooled);

    const int attn_smem = 2 * 256 * 32 * (int)sizeof(float);                    // 64 KB
    const int pair_smem = (2 * 32 * PSTR + 256 + 32 * 33) * (int)sizeof(float); // ~71.8 KB
    cudaFuncSetAttribute(attn2_kernel, cudaFuncAttributeMaxDynamicSharedMemorySize, attn_smem);
    cudaFuncSetAttribute(pair2_kernel, cudaFuncAttributeMaxDynamicSharedMemorySize, pair_smem);

    // 1. h partials = X @ enc_w1^T  (split-K: 256 blocks)
    gemm_h_kernel<<<dim3(HID / 64, ROWS / 64, 2), 128>>>(X, enc_w1, p_h, p_h2);
    // 2. r = relu(LN(h0+h1+enc_b1))  (warp-per-row)
    ln_relu_kernel<<<ROWS / 8, 256>>>(p_h, p_h2, enc_b1, ln_g, ln_b, p_r);
    // 3. mf = r @ enc_w2^T + enc_b2
    gemm_f32_kernel<<<dim3(HID / 64, ROWS / 64), 128>>>(
        p_r, HID, enc_w2, HID, enc_b2, p_mf, HID, HID);
    // 4. fused: qkv | a | b from mf
    gemm_fused_kernel<<<dim3(20, ROWS / 64), 128>>>(p_mf, in_proj_w, in_proj_b, con_w1,
                                                    p_qkv, p_a, p_b);
    // 5. attention -> ctx (fp32), probs (final, single write)
    attn2_kernel<<<128, 128, attn_smem>>>(p_qkv, p_ctx, p_probs);
    // 6. pooled_ctx (attended GEMM eliminated by linearity)
    pool_ctx_kernel<<<Bn, 256>>>(p_ctx, p_pc);
    // 7. pooled = pooled_ctx @ out_w^T + out_b
    head_gemm_kernel<<<Bn, 256>>>(p_pc, out_w, out_b, p_pooled);
    // 8. cons/hall
    head_mlp_kernel<<<16, 128>>>(p_pooled, cons_w1, cons_b1, cons_w2, cons_b2,
                                 hall_w1, hall_b1, hall_w2, hall_b2, out);
    // 9. attn_weights
    attnw_kernel<<<dim3(8, 8, 8), dim3(32, 8)>>>(p_probs, AWout);
    // 10. zero diagonal of M
    zero_diag_kernel<<<Bn, Sn>>>(Mout);
    // 11. pairwise M
    pair2_kernel<<<dim3(8, 8, 8), 256, pair_smem>>>(p_a, p_b, con_b1, con_w2, con_b2, Mout);
}

// round 17
// speedup vs baseline: 1.0915x; 1.0285x over previous
#include <cuda_runtime.h>
#include <cuda_bf16.h>
#include <cstdint>
#include <cstddef>

// ---------------------------------------------------------------------------
// Shapes (fixed): B=8, S=256, EMB=512, HID=256, NH=8, DH=32
// Outputs concat: cons[8] | hall[8] | M[8*256*256] | attn_weights[8*256*256]
// ---------------------------------------------------------------------------

#define Bn 8
#define Sn 256
#define EMB 512
#define HID 256
#define NHh 8
#define DHd 32
#define ROWS (Bn*Sn)          // 2048

typedef unsigned long long ULL;

// ===========================================================================
// f32x2 packed helpers
// ===========================================================================
__device__ __forceinline__ ULL pk2(float lo, float hi) {
    ULL r; asm("mov.b64 %0,{%1,%2};" : "=l"(r) : "f"(lo), "f"(hi)); return r;
}
__device__ __forceinline__ ULL fma2(ULL a, ULL b, ULL c) {
    ULL d; asm("fma.rn.f32x2 %0,%1,%2,%3;" : "=l"(d) : "l"(a), "l"(b), "l"(c)); return d;
}
__device__ __forceinline__ ULL mul2(ULL a, ULL b) {
    ULL d; asm("mul.rn.f32x2 %0,%1,%2;" : "=l"(d) : "l"(a), "l"(b)); return d;
}
__device__ __forceinline__ void unpk(ULL v, float& lo, float& hi) {
    asm("mov.b64 {%0,%1},%2;" : "=f"(lo), "=f"(hi) : "l"(v));
}

// ===========================================================================
// Scratch (__device__ globals; no allocs allowed)
// ===========================================================================
__device__ float g_h [ROWS*HID];     // h partial (K half 0)
__device__ float g_h2[ROWS*HID];     // h partial (K half 1)
__device__ float g_r [ROWS*HID];
__device__ float g_mf[ROWS*HID];
__device__ float g_qkv[ROWS*3*HID];
__device__ float g_ctx[ROWS*HID];
__device__ float g_a[ROWS*HID];
__device__ float g_b[ROWS*HID];
__device__ float g_probs[NHh*Bn*Sn*Sn];   // [h][b][t][s]
__device__ float g_pc[Bn*HID];            // pooled ctx
__device__ float g_pooled[Bn*HID];

// ===========================================================================
// f32x2 SIMT GEMM core (round-3/10 PROVEN inner loop; do not touch).
// ===========================================================================
__device__ __forceinline__ void gemm_core_f32(const float* __restrict__ Ablk, int lda,
                                              const float* __restrict__ Wblk, int ldw,
                                              const float* __restrict__ biasblk,
                                              float* __restrict__ Cblk,
                                              int ldc, int K)
{
    __shared__ __align__(16) float As[2][16][68];
    __shared__ __align__(16) float Ws[2][16][68];
    const int tid = threadIdx.x;
    const int lrow = tid & 63;
    const int lk = (tid >> 6) << 3;   // 0 or 8
    const float* Ap = Ablk + (size_t)lrow * lda + lk;
    const float* Wp = Wblk + (size_t)lrow * ldw + lk;
    const int tx = tid & 15;
    const int ty = tid >> 4;

    ULL acc[4][4];
#pragma unroll
    for (int u = 0; u < 4; u++)
#pragma unroll
        for (int j = 0; j < 4; j++) acc[u][j] = 0ULL;

    float4 a0 = *(const float4*)(Ap);
    float4 a1 = *(const float4*)(Ap + 4);
    float4 w0 = *(const float4*)(Wp);
    float4 w1 = *(const float4*)(Wp + 4);
    As[0][lk + 0][lrow] = a0.x; As[0][lk + 1][lrow] = a0.y;
    As[0][lk + 2][lrow] = a0.z; As[0][lk + 3][lrow] = a0.w;
    As[0][lk + 4][lrow] = a1.x; As[0][lk + 5][lrow] = a1.y;
    As[0][lk + 6][lrow] = a1.z; As[0][lk + 7][lrow] = a1.w;
    Ws[0][lk + 0][lrow] = w0.x; Ws[0][lk + 1][lrow] = w0.y;
    Ws[0][lk + 2][lrow] = w0.z; Ws[0][lk + 3][lrow] = w0.w;
    Ws[0][lk + 4][lrow] = w1.x; Ws[0][lk + 5][lrow] = w1.y;
    Ws[0][lk + 6][lrow] = w1.z; Ws[0][lk + 7][lrow] = w1.w;
    __syncthreads();

    const int nt = K >> 4;
    for (int t = 0; t < nt; ++t) {
        const int cur = t & 1;
        if (t + 1 < nt) {
            const float* Ap2 = Ap + ((t + 1) << 4);
            const float* Wp2 = Wp + ((t + 1) << 4);
            a0 = *(const float4*)(Ap2);
            a1 = *(const float4*)(Ap2 + 4);
            w0 = *(const float4*)(Wp2);
            w1 = *(const float4*)(Wp2 + 4);
        }
#pragma unroll
        for (int kk = 0; kk < 16; ++kk) {
            ulonglong2 aA = *(const ulonglong2*)&As[cur][kk][ty << 3];
            ulonglong2 aB = *(const ulonglong2*)&As[cur][kk][(ty << 3) + 4];
            float4 bf = *(const float4*)&Ws[cur][kk][tx << 2];
            ULL b0 = pk2(bf.x, bf.x);
            ULL b1 = pk2(bf.y, bf.y);
            ULL b2 = pk2(bf.z, bf.z);
            ULL b3 = pk2(bf.w, bf.w);
            ULL ar[4] = {aA.x, aA.y, aB.x, aB.y};
#pragma unroll
            for (int u = 0; u < 4; u++) {
                acc[u][0] = fma2(ar[u], b0, acc[u][0]);
                acc[u][1] = fma2(ar[u], b1, acc[u][1]);
                acc[u][2] = fma2(ar[u], b2, acc[u][2]);
                acc[u][3] = fma2(ar[u], b3, acc[u][3]);
            }
        }
        if (t + 1 < nt) {
            const int nb = (t + 1) & 1;
            As[nb][lk + 0][lrow] = a0.x; As[nb][lk + 1][lrow] = a0.y;
            As[nb][lk + 2][lrow] = a0.z; As[nb][lk + 3][lrow] = a0.w;
            As[nb][lk + 4][lrow] = a1.x; As[nb][lk + 5][lrow] = a1.y;
            As[nb][lk + 6][lrow] = a1.z; As[nb][lk + 7][lrow] = a1.w;
            Ws[nb][lk + 0][lrow] = w0.x; Ws[nb][lk + 1][lrow] = w0.y;
            Ws[nb][lk + 2][lrow] = w0.z; Ws[nb][lk + 3][lrow] = w0.w;
            Ws[nb][lk + 4][lrow] = w1.x; Ws[nb][lk + 5][lrow] = w1.y;
            Ws[nb][lk + 6][lrow] = w1.z; Ws[nb][lk + 7][lrow] = w1.w;
            __syncthreads();
        }
    }

    float4 bz = make_float4(0.f, 0.f, 0.f, 0.f);
    if (biasblk) bz = *(const float4*)(biasblk + (tx << 2));
#pragma unroll
    for (int u = 0; u < 4; u++) {
        float4 lo4, hi4;
        unpk(acc[u][0], lo4.x, hi4.x);
        unpk(acc[u][1], lo4.y, hi4.y);
        unpk(acc[u][2], lo4.z, hi4.z);
        unpk(acc[u][3], lo4.w, hi4.w);
        lo4.x += bz.x; lo4.y += bz.y; lo4.z += bz.z; lo4.w += bz.w;
        hi4.x += bz.x; hi4.y += bz.y; hi4.z += bz.z; hi4.w += bz.w;
        int r0 = (ty << 3) + 2 * u;
        *(float4*)(Cblk + (size_t)r0 * ldc + (tx << 2)) = lo4;
        *(float4*)(Cblk + (size_t)(r0 + 1) * ldc + (tx << 2)) = hi4;
    }
}

// h GEMM with K split in two halves (z = K half), partials to h0/h1, no bias
__global__ __launch_bounds__(128) void gemm_h_kernel(const float* __restrict__ X,
                                                     const float* __restrict__ w1,
                                                     float* __restrict__ h0,
                                                     float* __restrict__ h1)
{
    int row0 = blockIdx.y << 6;
    int col0 = blockIdx.x << 6;
    int kz = blockIdx.z;
    float* outp = kz ? h1 : h0;
    gemm_core_f32(X + (size_t)row0 * EMB + kz * 256, EMB,
                  w1 + (size_t)col0 * EMB + kz * 256, EMB,
                  nullptr,
                  outp + (size_t)row0 * HID + col0, HID, 256);
}

// generic GEMM: C[M,N] = A@W^T + bias
__global__ __launch_bounds__(128) void gemm_f32_kernel(const float* __restrict__ A, int lda,
                                                       const float* __restrict__ W, int ldw,
                                                       const float* __restrict__ bias,
                                                       float* __restrict__ C, int ldc, int K)
{
    int row0 = blockIdx.y << 6;
    int col0 = blockIdx.x << 6;
    gemm_core_f32(A + (size_t)row0 * lda, lda,
                  W + (size_t)col0 * ldw, ldw,
                  bias ? bias + col0 : nullptr,
                  C + (size_t)row0 * ldc + col0, ldc, K);
}

// fused: from mf compute qkv (tiles 0..11), a (12..15), b (16..19)
__global__ __launch_bounds__(128) void gemm_fused_kernel(const float* __restrict__ mf,
                                                         const float* __restrict__ in_proj_w,
                                                         const float* __restrict__ in_proj_b,
                                                         const float* __restrict__ con_w1,
                                                         float* __restrict__ qkv,
                                                         float* __restrict__ a,
                                                         float* __restrict__ b)
{
    int row0 = blockIdx.y << 6;
    int cb = blockIdx.x;
    const float* Wblk; const float* biasblk; float* Cblk; int ldw, ldc;
    if (cb < 12) {
        int n0 = cb << 6;
        Wblk = in_proj_w + (size_t)n0 * HID; ldw = HID;
        biasblk = in_proj_b + n0;
        Cblk = qkv + (size_t)row0 * (3 * HID) + n0; ldc = 3 * HID;
    } else if (cb < 16) {
        int n0 = (cb - 12) << 6;
        Wblk = con_w1 + (size_t)n0 * (2 * HID); ldw = 2 * HID;
        biasblk = nullptr;
        Cblk = a + (size_t)row0 * HID + n0; ldc = HID;
    } else {
        int n0 = (cb - 16) << 6;
        Wblk = con_w1 + (size_t)n0 * (2 * HID) + HID; ldw = 2 * HID;
        biasblk = nullptr;
        Cblk = b + (size_t)row0 * HID + n0; ldc = HID;
    }
    gemm_core_f32(mf + (size_t)row0 * HID, HID, Wblk, ldw, biasblk, Cblk, ldc, HID);
}

// ===========================================================================
// LayerNorm(256)+ReLU, warp-per-row; h = h0 + h1 + enc_b1 summed here.
// ===========================================================================
__global__ void ln_relu_kernel(const float* __restrict__ h0,
                               const float* __restrict__ h1,
                               const float* __restrict__ b1v,
                               const float* __restrict__ g,
                               const float* __restrict__ beta,
                               float* __restrict__ r)
{
    int row = (blockIdx.x << 3) + (threadIdx.x >> 5);
    int lane = threadIdx.x & 31;
    const float* p0 = h0 + (size_t)row * HID;
    const float* p1 = h1 + (size_t)row * HID;
    float v[8];
    float s = 0.f, s2 = 0.f;
#pragma unroll
    for (int j = 0; j < 8; j++) {
        int c = lane + (j << 5);
        float x = p0[c] + p1[c] + b1v[c];
        v[j] = x;
        s += x; s2 += x * x;
    }
#pragma unroll
    for (int o = 16; o; o >>= 1) {
        s  += __shfl_xor_sync(0xffffffffu, s, o);
        s2 += __shfl_xor_sync(0xffffffffu, s2, o);
    }
    float mu = s * (1.f / 256.f);
    float var = fmaxf(s2 * (1.f / 256.f) - mu * mu, 0.f);
    float rstd = rsqrtf(var + 1e-5f);
    float* rr = r + (size_t)row * HID;
#pragma unroll
    for (int j = 0; j < 8; j++) {
        int c = lane + (j << 5);
        float y = (v[j] - mu) * rstd * g[c] + beta[c];
        rr[c] = fmaxf(y, 0.f);
    }
}

// ===========================================================================
// MEGA kernel: attention + pairwise M, concurrent by grid partition.
//   blocks 0..63   : attention (b,h); 256 threads, one query per thread.
//   blocks 64..351 : pair tile (b, ti<=tj); 256 threads; diag folded.
// dynamic smem = pair size (71.8 KB) >= attention (64 KB).
// ===========================================================================
#define PSTR 260
#define NPAIR 36   // ti<=tj pairs of 8 tiles

__global__ __launch_bounds__(256) void mega_kernel(
    const float* __restrict__ qkv,
    float* __restrict__ ctx,
    float* __restrict__ probs,
    const float* __restrict__ ga, const float* __restrict__ gb,
    const float* __restrict__ b1, const float* __restrict__ w2,
    const float* __restrict__ b2, float* __restrict__ M)
{
    extern __shared__ float sm[];
    int tid = threadIdx.x;

    if (blockIdx.x < 64) {
        // ------------------- attention path (one query per thread) ---------
        float* Ks = sm;             // [256][32]
        float* Vs = sm + 256 * 32;  // [256][32]
        int bh = blockIdx.x;
        int b = bh >> 3, hd = bh & 7;
        int s = tid;
        const float* base = qkv + (size_t)(b * Sn) * (3 * HID) + hd * DHd;

        {   // K/V: one row per thread
            const float4* krow = (const float4*)(base + (size_t)tid * (3 * HID) + HID);
            const float4* vrow = (const float4*)(base + (size_t)tid * (3 * HID) + 2 * HID);
            float4* kd = (float4*)(Ks + tid * 32);
            float4* vd = (float4*)(Vs + tid * 32);
#pragma unroll
            for (int i = 0; i < 8; i++) { kd[i] = krow[i]; vd[i] = vrow[i]; }
        }
        ULL q2[16];
        {
            const ulonglong2* qrow = (const ulonglong2*)(base + (size_t)s * (3 * HID));
#pragma unroll
            for (int u = 0; u < 8; u++) {
                ulonglong2 qv = qrow[u];
                q2[2 * u] = qv.x; q2[2 * u + 1] = qv.y;
            }
        }
        __syncthreads();

        const float scale = 0.17677669529663687f;   // 1/sqrt(32)
        float m = -1e30f, l = 0.f;
        ULL acc2[16];
#pragma unroll
        for (int d = 0; d < 16; d++) acc2[d] = 0ULL;

        for (int t = 0; t < Sn; t++) {
            const ulonglong2* k4 = (const ulonglong2*)(Ks + t * 32);
            ULL sd2 = 0ULL;
#pragma unroll
            for (int u = 0; u < 8; u++) {
                ulonglong2 kv = k4[u];
                sd2 = fma2(q2[2 * u], kv.x, sd2);
                sd2 = fma2(q2[2 * u + 1], kv.y, sd2);
            }
            float slo, shi;
            unpk(sd2, slo, shi);
            float sd = (slo + shi) * scale;
            float mn = fmaxf(m, sd);
            float corr = __expf(m - mn);
            float p = __expf(sd - mn);
            l = l * corr + p;
            ULL corr2 = pk2(corr, corr);
            ULL p2 = pk2(p, p);
            const ulonglong2* v4 = (const ulonglong2*)(Vs + t * 32);
#pragma unroll
            for (int u = 0; u < 8; u++) {
                ulonglong2 vv = v4[u];
                acc2[2 * u]     = fma2(p2, vv.x, mul2(acc2[2 * u], corr2));
                acc2[2 * u + 1] = fma2(p2, vv.y, mul2(acc2[2 * u + 1], corr2));
            }
            m = mn;
        }
        float invl = 1.f / l;
        ULL invl2 = pk2(invl, invl);
        ulonglong2* crow = (ulonglong2*)(ctx + (size_t)(b * Sn + s) * HID + hd * DHd);
#pragma unroll
        for (int u = 0; u < 8; u++) {
            ulonglong2 ov;
            ov.x = mul2(acc2[2 * u], invl2);
            ov.y = mul2(acc2[2 * u + 1], invl2);
            crow[u] = ov;
        }

        // pass 2: recompute scores, write final probs/NH (coalesced over s)
        float* pb = probs + ((size_t)(hd * Bn + b) * Sn) * Sn + s;
        float c1 = invl * 0.125f;
        for (int t = 0; t < Sn; t++) {
            const ulonglong2* k4 = (const ulonglong2*)(Ks + t * 32);
            ULL sd2 = 0ULL;
#pragma unroll
            for (int u = 0; u < 8; u++) {
                ulonglong2 kv = k4[u];
                sd2 = fma2(q2[2 * u], kv.x, sd2);
                sd2 = fma2(q2[2 * u + 1], kv.y, sd2);
            }
            float slo, shi;
            unpk(sd2, slo, shi);
            float sd = (slo + shi) * scale;
            pb[(size_t)t * Sn] = __expf(sd - m) * c1;
        }
        return;
    }

    // ----------------------- pair path ------------------------------------
    {
        int i = blockIdx.x - 64;
        int b = i / NPAIR;
        int p = i - b * NPAIR;
        int ti = 0, rem = p;
        while (rem >= 8 - ti) { rem -= 8 - ti; ti++; }
        int tj = ti + rem;

        float* a_s = sm;                   // [32][PSTR]  (bias folded in)
        float* b_s = sm + 32 * PSTR;       // [32][PSTR]
        float* w2s = b_s + 32 * PSTR;      // [256]
        float* scs = w2s + 256;            // [32][33]
        {
            int r = tid >> 3;
            int cb = (tid & 7) * 32;
            const float4* asrc = (const float4*)(ga + (size_t)(b * Sn + ti * 32 + r) * HID + cb);
            const float4* bsrc = (const float4*)(gb + (size_t)(b * Sn + tj * 32 + r) * HID + cb);
#pragma unroll
            for (int u = 0; u < 8; u++) {
                int c = cb + u * 4;
                float4 av = asrc[u];
                float4 bb = *(const float4*)(b1 + c);
                av.x += bb.x; av.y += bb.y; av.z += bb.z; av.w += bb.w;
                *(float4*)&a_s[r * PSTR + c] = av;
                *(float4*)&b_s[r * PSTR + c] = bsrc[u];
            }
            w2s[tid] = w2[tid];
        }
        __syncthreads();

        int tx = tid & 31, ty = tid >> 5;
        float acc[4] = {0.f, 0.f, 0.f, 0.f};
        for (int c = 0; c < 256; c += 4) {
            float4 w = *(const float4*)&w2s[c];
            float4 bv = *(const float4*)&b_s[tx * PSTR + c];
#pragma unroll
            for (int ii = 0; ii < 4; ii++) {
                float4 av = *(const float4*)&a_s[(ty + 8 * ii) * PSTR + c];
                acc[ii] += fmaxf(av.x + bv.x, 0.f) * w.x
                         + fmaxf(av.y + bv.y, 0.f) * w.y
                         + fmaxf(av.z + bv.z, 0.f) * w.z
                         + fmaxf(av.w + bv.w, 0.f) * w.w;
            }
        }
        float bb2 = b2[0];
#pragma unroll
        for (int ii = 0; ii < 4; ii++) {
            int il = ty + 8 * ii;
            float sc = 1.f / (1.f + __expf(-(acc[ii] + bb2)));
            scs[il * 33 + tx] = ((ti * 32 + il) < (tj * 32 + tx)) ? sc : 0.f;
        }
        __syncthreads();

        float* Mb = M + (size_t)b * Sn * Sn;
        bool diag = (ti == tj);
#pragma unroll
        for (int ii = 0; ii < 4; ii++) {
            int il = ty + 8 * ii;
            if (!diag || il <= tx)   // diag tile: upper incl. zero diagonal
                Mb[(size_t)(ti * 32 + il) * Sn + tj * 32 + tx] = scs[il * 33 + tx];
            if (!diag || tx < il)    // diag tile: strict lower (transpose)
                Mb[(size_t)(tj * 32 + il) * Sn + ti * 32 + tx] = scs[tx * 33 + il];
        }
    }
}

// ===========================================================================
// attn_weights[b][s][t] = sum_h probs[h][b][t][s]
// ===========================================================================
__global__ void attnw_kernel(const float* __restrict__ probs,
                             float* __restrict__ out)
{
    __shared__ float tile[32][33];
    int b = blockIdx.z, t0 = blockIdx.x * 32, s0 = blockIdx.y * 32;
    int tx = threadIdx.x, ty = threadIdx.y;
#pragma unroll
    for (int r = 0; r < 4; r++) {
        int t = t0 + ty + r * 8;
        float sum = 0.f;
#pragma unroll
        for (int h = 0; h < 8; h++)
            sum += probs[((size_t)(h * Bn + b) * Sn + t) * Sn + s0 + tx];
        tile[ty + r * 8][tx] = sum;
    }
    __syncthreads();
#pragma unroll
    for (int r = 0; r < 4; r++) {
        int srow = s0 + ty + r * 8;
        out[((size_t)b * Sn + srow) * Sn + t0 + tx] = tile[tx][ty + r * 8];
    }
}

// ===========================================================================
// pooled_ctx[b][c] = mean_s ctx[b][s][c]; pooled via mini-GEMM (linearity).
// ===========================================================================
__global__ void pool_ctx_kernel(const float* __restrict__ ctx, float* __restrict__ pc)
{
    int b = blockIdx.x, c = threadIdx.x;
    float s = 0.f;
    for (int t = 0; t < Sn; t++) s += ctx[(size_t)(b * Sn + t) * HID + c];
    pc[b * HID + c] = s * (1.f / 256.f);
}

__global__ void head_gemm_kernel(const float* __restrict__ pc,
                                 const float* __restrict__ ow,
                                 const float* __restrict__ ob,
                                 float* __restrict__ pooled)
{
    int b = blockIdx.x;
    int tid = threadIdx.x;
    int warp = tid >> 5, lane = tid & 31;
    __shared__ float ps[256];
    ps[tid] = pc[b * HID + tid];
    __syncthreads();
    for (int c = warp; c < HID; c += 8) {
        const float* wrow = ow + (size_t)c * HID;
        float sum = 0.f;
#pragma unroll
        for (int j = 0; j < 8; j++) {
            int k = lane + (j << 5);
            sum += wrow[k] * ps[k];
        }
#pragma unroll
        for (int o = 16; o; o >>= 1) sum += __shfl_xor_sync(0xffffffffu, sum, o);
        if (lane == 0) pooled[b * HID + c] = sum + ob[c];
    }
}

__global__ void head_mlp_kernel(const float* __restrict__ pooled,
                                const float* __restrict__ cw1, const float* __restrict__ cb1,
                                const float* __restrict__ cw2, const float* __restrict__ cb2,
                                const float* __restrict__ hw1, const float* __restrict__ hb1,
                                const float* __restrict__ hw2, const float* __restrict__ hb2,
                                float* __restrict__ out)
{
    int b = blockIdx.x >> 1;
    int which = blockIdx.x & 1;
    const float* w1 = which ? hw1 : cw1;
    const float* b1 = which ? hb1 : cb1;
    const float* w2 = which ? hw2 : cw2;
    const float* b2 = which ? hb2 : cb2;
    int tid = threadIdx.x;
    __shared__ float p[256];
    p[tid] = pooled[b * HID + tid];
    p[tid + 128] = pooled[b * HID + tid + 128];
    __syncthreads();
    float acc = b1[tid];
    const float* wrow = w1 + (size_t)tid * HID;
#pragma unroll 8
    for (int k = 0; k < HID; k++) acc += p[k] * wrow[k];
    float v = fmaxf(acc, 0.f) * w2[tid];
#pragma unroll
    for (int o = 16; o; o >>= 1) v += __shfl_xor_sync(0xffffffffu, v, o);
    __shared__ float rs[4];
    if ((tid & 31) == 0) rs[tid >> 5] = v;
    __syncthreads();
    if (tid == 0) {
        float sum = rs[0] + rs[1] + rs[2] + rs[3] + b2[0];
        out[which * 8 + b] = 1.f / (1.f + __expf(-sum));
    }
}

// ===========================================================================
// Host launcher
// ===========================================================================
extern "C" void kernel_launch(void* const* d_in, const int* in_sizes, int n_in,
                              void* d_out, int out_size)
{
    (void)in_sizes; (void)n_in; (void)out_size;
    const float* X        = (const float*)d_in[0];
    const float* enc_w1   = (const float*)d_in[1];
    const float* enc_b1   = (const float*)d_in[2];
    const float* ln_g     = (const float*)d_in[3];
    const float* ln_b     = (const float*)d_in[4];
    const float* enc_w2   = (const float*)d_in[5];
    const float* enc_b2   = (const float*)d_in[6];
    const float* in_proj_w= (const float*)d_in[7];
    const float* in_proj_b= (const float*)d_in[8];
    const float* out_w    = (const float*)d_in[9];
    const float* out_b    = (const float*)d_in[10];
    const float* cons_w1  = (const float*)d_in[11];
    const float* cons_b1  = (const float*)d_in[12];
    const float* cons_w2  = (const float*)d_in[13];
    const float* cons_b2  = (const float*)d_in[14];
    const float* hall_w1  = (const float*)d_in[15];
    const float* hall_b1  = (const float*)d_in[16];
    const float* hall_w2  = (const float*)d_in[17];
    const float* hall_b2  = (const float*)d_in[18];
    const float* con_w1   = (const float*)d_in[19];
    const float* con_b1   = (const float*)d_in[20];
    const float* con_w2   = (const float*)d_in[21];
    const float* con_b2   = (const float*)d_in[22];

    float* out = (float*)d_out;
    float* Mout  = out + 16;
    float* AWout = out + 16 + Bn * Sn * Sn;

    float *p_h, *p_h2, *p_r, *p_mf, *p_qkv, *p_ctx, *p_a, *p_b, *p_probs, *p_pc, *p_pooled;
    cudaGetSymbolAddress((void**)&p_h, g_h);
    cudaGetSymbolAddress((void**)&p_h2, g_h2);
    cudaGetSymbolAddress((void**)&p_r, g_r);
    cudaGetSymbolAddress((void**)&p_mf, g_mf);
    cudaGetSymbolAddress((void**)&p_qkv, g_qkv);
    cudaGetSymbolAddress((void**)&p_ctx, g_ctx);
    cudaGetSymbolAddress((void**)&p_a, g_a);
    cudaGetSymbolAddress((void**)&p_b, g_b);
    cudaGetSymbolAddress((void**)&p_probs, g_probs);
    cudaGetSymbolAddress((void**)&p_pc, g_pc);
    cudaGetSymbolAddress((void**)&p_pooled, g_pooled);

    const int mega_smem = (2 * 32 * PSTR + 256 + 32 * 33) * (int)sizeof(float); // ~71.8 KB
    cudaFuncSetAttribute(mega_kernel, cudaFuncAttributeMaxDynamicSharedMemorySize, mega_smem);

    // 1. h partials = X @ enc_w1^T  (split-K: 256 blocks)
    gemm_h_kernel<<<dim3(HID / 64, ROWS / 64, 2), 128>>>(X, enc_w1, p_h, p_h2);
    // 2. r = relu(LN(h0+h1+enc_b1))  (warp-per-row)
    ln_relu_kernel<<<ROWS / 8, 256>>>(p_h, p_h2, enc_b1, ln_g, ln_b, p_r);
    // 3. mf = r @ enc_w2^T + enc_b2
    gemm_f32_kernel<<<dim3(HID / 64, ROWS / 64), 128>>>(
        p_r, HID, enc_w2, HID, enc_b2, p_mf, HID, HID);
    // 4. fused: qkv | a | b from mf
    gemm_fused_kernel<<<dim3(20, ROWS / 64), 128>>>(p_mf, in_proj_w, in_proj_b, con_w1,
                                                    p_qkv, p_a, p_b);
    // 5. MEGA: attention (64 blocks) + pairwise M (288 blocks), concurrent
    mega_kernel<<<64 + Bn * NPAIR, 256, mega_smem>>>(
        p_qkv, p_ctx, p_probs, p_a, p_b, con_b1, con_w2, con_b2, Mout);
    // 6. pooled_ctx
    pool_ctx_kernel<<<Bn, 256>>>(p_ctx, p_pc);
    // 7. pooled = pooled_ctx @ out_w^T + out_b
    head_gemm_kernel<<<Bn, 256>>>(p_pc, out_w, out_b, p_pooled);
    // 8. cons/hall
    head_mlp_kernel<<<16, 128>>>(p_pooled, cons_w1, cons_b1, cons_w2, cons_b2,
                                 hall_w1, hall_b1, hall_w2, hall_b2, out);
    // 9. attn_weights
    attnw_kernel<<<dim3(8, 8, 8), dim3(32, 8)>>>(p_probs, AWout);
}